// round 2
// baseline (speedup 1.0000x reference)
#include <cuda_runtime.h>
#include <cstdint>

// ---------------------------------------------------------------------------
// GraphConvolution: out[dst] += w_e * (X @ W)[src]
//   X: [N=100000, 256] f32    W: [256, 128] f32
//   edge_index: [2, E=1600000]  (row0 = dst, row1 = src) -- int32 OR int64
//   edge_weight: f32 [E]
//   out: f32 [N, 128]
// ---------------------------------------------------------------------------

#define N_NODES_MAX 100000
#define IN_F  256
#define OUT_F 128

__device__ float g_support[(size_t)N_NODES_MAX * OUT_F];
__device__ int   g_idx_is64;

// ---------------- dtype detection for edge_index ----------------------------
// int64 little-endian with values in [0, 2^31): odd 32-bit words are all 0.
// int32 random node ids: 32 consecutive odd words all zero ~ impossible.
__global__ void detect_idx_kernel(const unsigned int* __restrict__ raw)
{
    if (threadIdx.x == 0 && blockIdx.x == 0) {
        int is64 = 1;
        #pragma unroll
        for (int i = 1; i < 64; i += 2)
            if (raw[i] != 0u) { is64 = 0; break; }
        g_idx_is64 = is64;
    }
}

// ---------------- GEMM: 64x128 block tile, 16 k-slice, 8x4 thread tile ------
#define BM 64
#define BN 128
#define BK 16

__global__ __launch_bounds__(256) void gemm_kernel(
    const float* __restrict__ X, const float* __restrict__ W,
    float* __restrict__ S, int M)
{
    __shared__ float As[BK][BM];      // transposed A slice
    __shared__ float Bs[BK][BN];

    const int t  = threadIdx.x;
    const int m0 = blockIdx.x * BM;
    const int tx = t & 31;            // N dir: 32 threads * TN=4 = 128
    const int ty = t >> 5;            // M dir: 8 threads  * TM=8 = 64

    float acc[8][4];
    #pragma unroll
    for (int i = 0; i < 8; i++)
        #pragma unroll
        for (int j = 0; j < 4; j++) acc[i][j] = 0.0f;

    const int arow = t >> 2;          // 0..63
    const int acol = (t & 3) * 4;     // 0,4,8,12

    for (int k0 = 0; k0 < IN_F; k0 += BK) {
        // --- load A tile (64 x 16), transposed into As[k][m] ---
        float4 av;
        if (m0 + arow < M) {
            av = *reinterpret_cast<const float4*>(
                X + (size_t)(m0 + arow) * IN_F + k0 + acol);
        } else {
            av = make_float4(0.f, 0.f, 0.f, 0.f);
        }
        As[acol + 0][arow] = av.x;
        As[acol + 1][arow] = av.y;
        As[acol + 2][arow] = av.z;
        As[acol + 3][arow] = av.w;

        // --- load B tile (16 x 128) ---
        #pragma unroll
        for (int i = 0; i < 2; i++) {
            int f  = t + i * 256;
            int br = f >> 5;
            int bc = (f & 31) * 4;
            *reinterpret_cast<float4*>(&Bs[br][bc]) =
                *reinterpret_cast<const float4*>(
                    W + (size_t)(k0 + br) * OUT_F + bc);
        }
        __syncthreads();

        // --- compute ---
        #pragma unroll
        for (int k = 0; k < BK; k++) {
            float4 a0 = *reinterpret_cast<const float4*>(&As[k][ty * 8]);
            float4 a1 = *reinterpret_cast<const float4*>(&As[k][ty * 8 + 4]);
            float4 b  = *reinterpret_cast<const float4*>(&Bs[k][tx * 4]);
            float a[8]  = {a0.x, a0.y, a0.z, a0.w, a1.x, a1.y, a1.z, a1.w};
            float bb[4] = {b.x, b.y, b.z, b.w};
            #pragma unroll
            for (int i = 0; i < 8; i++)
                #pragma unroll
                for (int j = 0; j < 4; j++)
                    acc[i][j] = fmaf(a[i], bb[j], acc[i][j]);
        }
        __syncthreads();
    }

    // --- store ---
    #pragma unroll
    for (int i = 0; i < 8; i++) {
        int m = m0 + ty * 8 + i;
        if (m < M) {
            float4 v = make_float4(acc[i][0], acc[i][1], acc[i][2], acc[i][3]);
            *reinterpret_cast<float4*>(S + (size_t)m * OUT_F + tx * 4) = v;
        }
    }
}

// ---------------- Scatter: warp handles 32 edges, 128 floats each -----------
__global__ __launch_bounds__(256) void scatter_kernel(
    const void* __restrict__ ei_raw, const float* __restrict__ ew,
    const float* __restrict__ S, float* __restrict__ out, int E)
{
    const int warp = (blockIdx.x * blockDim.x + threadIdx.x) >> 5;
    const int lane = threadIdx.x & 31;
    const int e0 = warp * 32;
    if (e0 >= E) return;

    const int is64 = g_idx_is64;

    int d = 0, s = 0;
    float w = 0.0f;
    const int my_e = e0 + lane;
    if (my_e < E) {
        if (is64) {
            const long long* ei = (const long long*)ei_raw;
            d = (int)ei[my_e];                 // dst
            s = (int)ei[(size_t)E + my_e];     // src
        } else {
            const int* ei = (const int*)ei_raw;
            d = ei[my_e];                      // dst
            s = ei[(size_t)E + my_e];          // src
        }
        w = ew[my_e];
    }

    const int n = (E - e0 < 32) ? (E - e0) : 32;
    for (int j = 0; j < n; j++) {
        int   sj = __shfl_sync(0xffffffffu, s, j);
        int   dj = __shfl_sync(0xffffffffu, d, j);
        float wj = __shfl_sync(0xffffffffu, w, j);

        float4 v = *reinterpret_cast<const float4*>(
            S + (size_t)sj * OUT_F + lane * 4);
        v.x *= wj; v.y *= wj; v.z *= wj; v.w *= wj;

        float* p = out + (size_t)dj * OUT_F + lane * 4;
        asm volatile(
            "red.global.add.v4.f32 [%0], {%1, %2, %3, %4};"
            :: "l"(p), "f"(v.x), "f"(v.y), "f"(v.z), "f"(v.w)
            : "memory");
    }
}

// ---------------------------------------------------------------------------
extern "C" void kernel_launch(void* const* d_in, const int* in_sizes, int n_in,
                              void* d_out, int out_size)
{
    const float* X  = (const float*)d_in[0];
    const void*  EI = d_in[1];
    const float* EW = (const float*)d_in[2];
    const float* W  = (const float*)d_in[3];
    float*       O  = (float*)d_out;

    const int M = out_size / OUT_F;       // number of nodes
    const int E = in_sizes[2];            // number of edges (from edge_weight)

    float* S;
    cudaGetSymbolAddress((void**)&S, g_support);

    // zero the output (poisoned by harness)
    cudaMemsetAsync(O, 0, (size_t)out_size * sizeof(float), 0);

    // detect edge_index dtype (int32 vs int64)
    detect_idx_kernel<<<1, 32>>>((const unsigned int*)EI);

    // support = X @ W
    gemm_kernel<<<(M + BM - 1) / BM, 256>>>(X, W, S, M);

    // out[dst] += w * support[src]
    const int edges_per_block = (256 / 32) * 32;   // 8 warps * 32 edges
    const int nblocks = (E + edges_per_block - 1) / edges_per_block;
    scatter_kernel<<<nblocks, 256>>>(EI, EW, S, O, E);
}

// round 4
// speedup vs baseline: 1.3025x; 1.3025x over previous
#include <cuda_runtime.h>
#include <cstdint>

// ---------------------------------------------------------------------------
// GraphConvolution: out[dst] += w_e * (X @ W)[src]
//   X: [N=100000, 256] f32   W: [256, 128] f32
//   edge_index: [2, E] int32 (detected; int64 fallback)  edge_weight: f32 [E]
// R4: GEMM via warp-level mma.sync tf32 (sm_80+ PTX; no arch-suffix gate).
// ---------------------------------------------------------------------------

#define N_NODES_MAX 100000
#define IN_F  256
#define OUT_F 128

__device__ float g_support[(size_t)N_NODES_MAX * OUT_F];
__device__ int   g_idx_is64;

// ---------------- dtype detection for edge_index ----------------------------
__global__ void detect_idx_kernel(const unsigned int* __restrict__ raw)
{
    if (threadIdx.x == 0 && blockIdx.x == 0) {
        int is64 = 1;
        #pragma unroll
        for (int i = 1; i < 64; i += 2)
            if (raw[i] != 0u) { is64 = 0; break; }
        g_idx_is64 = is64;
    }
}

// ---------------- tf32 helpers -----------------------------------------------
__device__ __forceinline__ uint32_t f2tf32(float f) {
    uint32_t u;
    asm("cvt.rna.tf32.f32 %0, %1;" : "=r"(u) : "f"(f));
    return u;
}

__device__ __forceinline__ void mma_tf32(
    float& c0, float& c1, float& c2, float& c3,
    uint32_t a0, uint32_t a1, uint32_t a2, uint32_t a3,
    uint32_t b0, uint32_t b1)
{
    asm volatile(
        "mma.sync.aligned.m16n8k8.row.col.f32.tf32.tf32.f32 "
        "{%0,%1,%2,%3}, {%4,%5,%6,%7}, {%8,%9}, {%0,%1,%2,%3};"
        : "+f"(c0), "+f"(c1), "+f"(c2), "+f"(c3)
        : "r"(a0), "r"(a1), "r"(a2), "r"(a3), "r"(b0), "r"(b1));
}

// ---------------- GEMM: 128x128 CTA tile, tf32 mma.sync ----------------------
// 8 warps in 4(M) x 2(N); each warp: 32x64 = 2x8 tiles of m16n8, k8 steps.
#define KC 32                 // K chunk
#define PAD 36                // smem row stride (floats)

__global__ __launch_bounds__(256) void gemm_mma_kernel(
    const float* __restrict__ X, const float* __restrict__ W,
    float* __restrict__ S, int M)
{
    __shared__ uint32_t As[128][PAD];   // [m][k] tf32 bits
    __shared__ uint32_t Bs[128][PAD];   // [n][k] tf32 bits

    const int t    = threadIdx.x;
    const int w    = t >> 5;
    const int lane = t & 31;
    const int g    = lane >> 2;        // groupID 0..7
    const int tig  = lane & 3;         // thread-in-group 0..3
    const int wm   = (w & 3) * 32;     // warp M offset
    const int wn   = (w >> 2) * 64;    // warp N offset
    const int m0   = blockIdx.x * 128;

    float acc[2][8][4];
    #pragma unroll
    for (int mi = 0; mi < 2; mi++)
        #pragma unroll
        for (int ni = 0; ni < 8; ni++)
            #pragma unroll
            for (int r = 0; r < 4; r++) acc[mi][ni][r] = 0.0f;

    for (int k0 = 0; k0 < IN_F; k0 += KC) {
        // --- A chunk: X[m0..m0+127][k0..k0+31] -> As[m][k], cvt tf32 ---
        #pragma unroll
        for (int i = 0; i < 4; i++) {
            int idx = t + i * 256;         // 1024 float4 slots
            int r   = idx >> 3;            // 8 float4 per 32-float row
            int c   = (idx & 7) * 4;
            float4 v = make_float4(0.f, 0.f, 0.f, 0.f);
            if (m0 + r < M)
                v = *reinterpret_cast<const float4*>(
                        X + (size_t)(m0 + r) * IN_F + k0 + c);
            As[r][c + 0] = f2tf32(v.x);
            As[r][c + 1] = f2tf32(v.y);
            As[r][c + 2] = f2tf32(v.z);
            As[r][c + 3] = f2tf32(v.w);
        }
        // --- B chunk: W[k0..k0+31][0..127] -> Bs[n][k] (transpose), cvt ---
        #pragma unroll
        for (int i = 0; i < 16; i++) {
            int idx = t + i * 256;         // 4096 scalars
            int k   = idx >> 7;
            int n   = idx & 127;
            Bs[n][k] = f2tf32(W[(size_t)(k0 + k) * OUT_F + n]);
        }
        __syncthreads();

        // --- compute: 4 k-steps of 8 ---
        #pragma unroll
        for (int ks = 0; ks < 4; ks++) {
            const int k = ks * 8;
            uint32_t a[2][4];
            #pragma unroll
            for (int mi = 0; mi < 2; mi++) {
                int mr = wm + mi * 16 + g;
                a[mi][0] = As[mr    ][k + tig];
                a[mi][1] = As[mr + 8][k + tig];
                a[mi][2] = As[mr    ][k + tig + 4];
                a[mi][3] = As[mr + 8][k + tig + 4];
            }
            uint32_t b[8][2];
            #pragma unroll
            for (int ni = 0; ni < 8; ni++) {
                int nr = wn + ni * 8 + g;
                b[ni][0] = Bs[nr][k + tig];
                b[ni][1] = Bs[nr][k + tig + 4];
            }
            #pragma unroll
            for (int mi = 0; mi < 2; mi++)
                #pragma unroll
                for (int ni = 0; ni < 8; ni++)
                    mma_tf32(acc[mi][ni][0], acc[mi][ni][1],
                             acc[mi][ni][2], acc[mi][ni][3],
                             a[mi][0], a[mi][1], a[mi][2], a[mi][3],
                             b[ni][0], b[ni][1]);
        }
        __syncthreads();
    }

    // --- epilogue: write 32x64 per warp ---
    #pragma unroll
    for (int mi = 0; mi < 2; mi++) {
        int r0 = m0 + wm + mi * 16 + g;
        #pragma unroll
        for (int ni = 0; ni < 8; ni++) {
            int c = wn + ni * 8 + tig * 2;
            if (r0 < M)
                *reinterpret_cast<float2*>(S + (size_t)r0 * OUT_F + c) =
                    make_float2(acc[mi][ni][0], acc[mi][ni][1]);
            if (r0 + 8 < M)
                *reinterpret_cast<float2*>(S + (size_t)(r0 + 8) * OUT_F + c) =
                    make_float2(acc[mi][ni][2], acc[mi][ni][3]);
        }
    }
}

// ---------------- Scatter: warp handles 32 edges, 128 floats each -----------
__global__ __launch_bounds__(256) void scatter_kernel(
    const void* __restrict__ ei_raw, const float* __restrict__ ew,
    const float* __restrict__ S, float* __restrict__ out, int E)
{
    const int warp = (blockIdx.x * blockDim.x + threadIdx.x) >> 5;
    const int lane = threadIdx.x & 31;
    const int e0 = warp * 32;
    if (e0 >= E) return;

    const int is64 = g_idx_is64;

    int d = 0, s = 0;
    float w = 0.0f;
    const int my_e = e0 + lane;
    if (my_e < E) {
        if (is64) {
            const long long* ei = (const long long*)ei_raw;
            d = (int)ei[my_e];
            s = (int)ei[(size_t)E + my_e];
        } else {
            const int* ei = (const int*)ei_raw;
            d = ei[my_e];
            s = ei[(size_t)E + my_e];
        }
        w = ew[my_e];
    }

    const int n = (E - e0 < 32) ? (E - e0) : 32;
    for (int j = 0; j < n; j++) {
        int   sj = __shfl_sync(0xffffffffu, s, j);
        int   dj = __shfl_sync(0xffffffffu, d, j);
        float wj = __shfl_sync(0xffffffffu, w, j);

        float4 v = *reinterpret_cast<const float4*>(
            S + (size_t)sj * OUT_F + lane * 4);
        v.x *= wj; v.y *= wj; v.z *= wj; v.w *= wj;

        float* p = out + (size_t)dj * OUT_F + lane * 4;
        asm volatile(
            "red.global.add.v4.f32 [%0], {%1, %2, %3, %4};"
            :: "l"(p), "f"(v.x), "f"(v.y), "f"(v.z), "f"(v.w)
            : "memory");
    }
}

// ---------------------------------------------------------------------------
extern "C" void kernel_launch(void* const* d_in, const int* in_sizes, int n_in,
                              void* d_out, int out_size)
{
    const float* X  = (const float*)d_in[0];
    const void*  EI = d_in[1];
    const float* EW = (const float*)d_in[2];
    const float* W  = (const float*)d_in[3];
    float*       O  = (float*)d_out;

    const int M = out_size / OUT_F;
    const int E = in_sizes[2];

    float* S;
    cudaGetSymbolAddress((void**)&S, g_support);

    cudaMemsetAsync(O, 0, (size_t)out_size * sizeof(float), 0);
    detect_idx_kernel<<<1, 32>>>((const unsigned int*)EI);

    gemm_mma_kernel<<<(M + 127) / 128, 256>>>(X, W, S, M);

    const int edges_per_block = (256 / 32) * 32;
    const int nblocks = (E + edges_per_block - 1) / edges_per_block;
    scatter_kernel<<<nblocks, 256>>>(EI, EW, S, O, E);
}

// round 5
// speedup vs baseline: 1.5322x; 1.1763x over previous
#include <cuda_runtime.h>
#include <cstdint>

// ---------------------------------------------------------------------------
// GraphConvolution: out[dst] += w_e * (X @ W)[src]
// R5: dst-bucketed scatter (histogram + scan + placement + warp-per-node
//     register aggregation, plain stores) replaces global atomics.
//     GEMM: tf32 mma.sync (unchanged from R4).
// Launch order (8/call) puts gemm at global ncu slot 5.
// ---------------------------------------------------------------------------

#define N_NODES_MAX 100000
#define E_MAX       1600000
#define IN_F  256
#define OUT_F 128

__device__ float g_support[(size_t)N_NODES_MAX * OUT_F];
__device__ int   g_idx_is64;
__device__ int   g_count[N_NODES_MAX];
__device__ int   g_offsets[N_NODES_MAX];
__device__ int   g_cursor[N_NODES_MAX];
__device__ int   g_bsum[1024];
__device__ uint2 g_edges[E_MAX];            // (src, w bits), dst-bucketed

// ---------------- 0: zero g_count + dtype detection --------------------------
__global__ void zero_detect_kernel(const unsigned int* __restrict__ raw, int M)
{
    int i = blockIdx.x * blockDim.x + threadIdx.x;
    if (i < M) g_count[i] = 0;
    if (blockIdx.x == 0 && threadIdx.x == 0) {
        int is64 = 1;
        #pragma unroll
        for (int k = 1; k < 64; k += 2)
            if (raw[k] != 0u) { is64 = 0; break; }
        g_idx_is64 = is64;
    }
}

// ---------------- 1: histogram over dst --------------------------------------
__global__ void hist_kernel(const void* __restrict__ ei_raw, int E)
{
    int e = blockIdx.x * blockDim.x + threadIdx.x;
    if (e >= E) return;
    int d = g_idx_is64 ? (int)((const long long*)ei_raw)[e]
                       : ((const int*)ei_raw)[e];
    atomicAdd(&g_count[d], 1);
}

// ---------------- 2/3/4: exclusive prefix sum of g_count ---------------------
__global__ __launch_bounds__(1024) void scan1_kernel(int M)
{
    __shared__ int sh[1024];
    const int t = threadIdx.x;
    const int i = blockIdx.x * 1024 + t;
    int v = (i < M) ? g_count[i] : 0;
    sh[t] = v; __syncthreads();
    #pragma unroll
    for (int off = 1; off < 1024; off <<= 1) {
        int x = (t >= off) ? sh[t - off] : 0;
        __syncthreads(); sh[t] += x; __syncthreads();
    }
    if (i < M) g_offsets[i] = sh[t] - v;
    if (t == 1023) g_bsum[blockIdx.x] = sh[1023];
}

__global__ __launch_bounds__(1024) void scan2_kernel(int nb)
{
    __shared__ int sh[1024];
    const int t = threadIdx.x;
    int v = (t < nb) ? g_bsum[t] : 0;
    sh[t] = v; __syncthreads();
    #pragma unroll
    for (int off = 1; off < 1024; off <<= 1) {
        int x = (t >= off) ? sh[t - off] : 0;
        __syncthreads(); sh[t] += x; __syncthreads();
    }
    if (t < nb) g_bsum[t] = sh[t] - v;   // exclusive block prefix
}

__global__ void scan3_kernel(int M)
{
    int i = blockIdx.x * blockDim.x + threadIdx.x;
    if (i >= M) return;
    int o = g_offsets[i] + g_bsum[i >> 10];
    g_offsets[i] = o;
    g_cursor[i]  = o;
}

// ---------------- 6: place edges into dst buckets -----------------------------
__global__ void place_kernel(const void* __restrict__ ei_raw,
                             const float* __restrict__ ew, int E)
{
    int e = blockIdx.x * blockDim.x + threadIdx.x;
    if (e >= E) return;
    int d, s;
    if (g_idx_is64) {
        const long long* ei = (const long long*)ei_raw;
        d = (int)ei[e]; s = (int)ei[(size_t)E + e];
    } else {
        const int* ei = (const int*)ei_raw;
        d = ei[e]; s = ei[(size_t)E + e];
    }
    int pos = atomicAdd(&g_cursor[d], 1);
    g_edges[pos] = make_uint2((unsigned)s, __float_as_uint(ew[e]));
}

// ---------------- tf32 helpers -----------------------------------------------
__device__ __forceinline__ uint32_t f2tf32(float f) {
    uint32_t u;
    asm("cvt.rna.tf32.f32 %0, %1;" : "=r"(u) : "f"(f));
    return u;
}
__device__ __forceinline__ void mma_tf32(
    float& c0, float& c1, float& c2, float& c3,
    uint32_t a0, uint32_t a1, uint32_t a2, uint32_t a3,
    uint32_t b0, uint32_t b1)
{
    asm volatile(
        "mma.sync.aligned.m16n8k8.row.col.f32.tf32.tf32.f32 "
        "{%0,%1,%2,%3}, {%4,%5,%6,%7}, {%8,%9}, {%0,%1,%2,%3};"
        : "+f"(c0), "+f"(c1), "+f"(c2), "+f"(c3)
        : "r"(a0), "r"(a1), "r"(a2), "r"(a3), "r"(b0), "r"(b1));
}

// ---------------- 5: GEMM 128x128 CTA tile, tf32 mma.sync --------------------
#define KC 32
#define PAD 36

__global__ __launch_bounds__(256) void gemm_mma_kernel(
    const float* __restrict__ X, const float* __restrict__ W,
    float* __restrict__ S, int M)
{
    __shared__ uint32_t As[128][PAD];
    __shared__ uint32_t Bs[128][PAD];

    const int t    = threadIdx.x;
    const int w    = t >> 5;
    const int lane = t & 31;
    const int g    = lane >> 2;
    const int tig  = lane & 3;
    const int wm   = (w & 3) * 32;
    const int wn   = (w >> 2) * 64;
    const int m0   = blockIdx.x * 128;

    float acc[2][8][4];
    #pragma unroll
    for (int mi = 0; mi < 2; mi++)
        #pragma unroll
        for (int ni = 0; ni < 8; ni++)
            #pragma unroll
            for (int r = 0; r < 4; r++) acc[mi][ni][r] = 0.0f;

    for (int k0 = 0; k0 < IN_F; k0 += KC) {
        #pragma unroll
        for (int i = 0; i < 4; i++) {
            int idx = t + i * 256;
            int r   = idx >> 3;
            int c   = (idx & 7) * 4;
            float4 v = make_float4(0.f, 0.f, 0.f, 0.f);
            if (m0 + r < M)
                v = *reinterpret_cast<const float4*>(
                        X + (size_t)(m0 + r) * IN_F + k0 + c);
            As[r][c + 0] = f2tf32(v.x);
            As[r][c + 1] = f2tf32(v.y);
            As[r][c + 2] = f2tf32(v.z);
            As[r][c + 3] = f2tf32(v.w);
        }
        #pragma unroll
        for (int i = 0; i < 16; i++) {
            int idx = t + i * 256;
            int k   = idx >> 7;
            int n   = idx & 127;
            Bs[n][k] = f2tf32(W[(size_t)(k0 + k) * OUT_F + n]);
        }
        __syncthreads();

        #pragma unroll
        for (int ks = 0; ks < 4; ks++) {
            const int k = ks * 8;
            uint32_t a[2][4];
            #pragma unroll
            for (int mi = 0; mi < 2; mi++) {
                int mr = wm + mi * 16 + g;
                a[mi][0] = As[mr    ][k + tig];
                a[mi][1] = As[mr + 8][k + tig];
                a[mi][2] = As[mr    ][k + tig + 4];
                a[mi][3] = As[mr + 8][k + tig + 4];
            }
            uint32_t b[8][2];
            #pragma unroll
            for (int ni = 0; ni < 8; ni++) {
                int nr = wn + ni * 8 + g;
                b[ni][0] = Bs[nr][k + tig];
                b[ni][1] = Bs[nr][k + tig + 4];
            }
            #pragma unroll
            for (int mi = 0; mi < 2; mi++)
                #pragma unroll
                for (int ni = 0; ni < 8; ni++)
                    mma_tf32(acc[mi][ni][0], acc[mi][ni][1],
                             acc[mi][ni][2], acc[mi][ni][3],
                             a[mi][0], a[mi][1], a[mi][2], a[mi][3],
                             b[ni][0], b[ni][1]);
        }
        __syncthreads();
    }

    #pragma unroll
    for (int mi = 0; mi < 2; mi++) {
        int r0 = m0 + wm + mi * 16 + g;
        #pragma unroll
        for (int ni = 0; ni < 8; ni++) {
            int c = wn + ni * 8 + tig * 2;
            if (r0 < M)
                *reinterpret_cast<float2*>(S + (size_t)r0 * OUT_F + c) =
                    make_float2(acc[mi][ni][0], acc[mi][ni][1]);
            if (r0 + 8 < M)
                *reinterpret_cast<float2*>(S + (size_t)(r0 + 8) * OUT_F + c) =
                    make_float2(acc[mi][ni][2], acc[mi][ni][3]);
        }
    }
}

// ---------------- 7: warp-per-node aggregation --------------------------------
__global__ __launch_bounds__(256) void aggregate_kernel(
    const float* __restrict__ S, float* __restrict__ out, int M)
{
    const int node = (blockIdx.x * blockDim.x + threadIdx.x) >> 5;
    const int lane = threadIdx.x & 31;
    if (node >= M) return;

    const int start = g_offsets[node];
    const int cnt   = g_count[node];

    float4 acc = make_float4(0.f, 0.f, 0.f, 0.f);

    for (int b = 0; b < cnt; b += 32) {
        const int nb = (cnt - b < 32) ? (cnt - b) : 32;
        uint2 p = make_uint2(0u, 0u);
        if (lane < nb) p = g_edges[start + b + lane];

        for (int j = 0; j < nb; j++) {
            unsigned sj = __shfl_sync(0xffffffffu, p.x, j);
            float    wj = __uint_as_float(__shfl_sync(0xffffffffu, p.y, j));
            float4 v = *reinterpret_cast<const float4*>(
                S + (size_t)sj * OUT_F + lane * 4);
            acc.x = fmaf(wj, v.x, acc.x);
            acc.y = fmaf(wj, v.y, acc.y);
            acc.z = fmaf(wj, v.z, acc.z);
            acc.w = fmaf(wj, v.w, acc.w);
        }
    }
    *reinterpret_cast<float4*>(out + (size_t)node * OUT_F + lane * 4) = acc;
}

// ---------------------------------------------------------------------------
extern "C" void kernel_launch(void* const* d_in, const int* in_sizes, int n_in,
                              void* d_out, int out_size)
{
    const float* X  = (const float*)d_in[0];
    const void*  EI = d_in[1];
    const float* EW = (const float*)d_in[2];
    const float* W  = (const float*)d_in[3];
    float*       O  = (float*)d_out;

    const int M = out_size / OUT_F;
    const int E = in_sizes[2];

    float* S;
    cudaGetSymbolAddress((void**)&S, g_support);

    const int nb1024 = (M + 1023) / 1024;

    // launch order fixed so gemm is global launch index 5 under ncu -s 5
    zero_detect_kernel<<<(M + 255) / 256, 256>>>((const unsigned int*)EI, M); // 0
    hist_kernel<<<(E + 255) / 256, 256>>>(EI, E);                             // 1
    scan1_kernel<<<nb1024, 1024>>>(M);                                        // 2
    scan2_kernel<<<1, 1024>>>(nb1024);                                        // 3
    scan3_kernel<<<(M + 255) / 256, 256>>>(M);                                // 4
    gemm_mma_kernel<<<(M + 127) / 128, 256>>>(X, W, S, M);                    // 5
    place_kernel<<<(E + 255) / 256, 256>>>(EI, EW, E);                        // 6
    aggregate_kernel<<<(M * 32 + 255) / 256, 256>>>(S, O, M);                 // 7
}

// round 6
// speedup vs baseline: 1.6174x; 1.0556x over previous
#include <cuda_runtime.h>
#include <cstdint>

// ---------------------------------------------------------------------------
// GraphConvolution: out[dst] += w_e * (X @ W)[src]
// R6: fork-join graph capture — GEMM branch || edge-bucketing branch, join at
//     warp-per-node aggregation. Unroll-4 gather for MLP. memset for counts.
// ---------------------------------------------------------------------------

#define N_NODES_MAX 100000
#define E_MAX       1600000
#define IN_F  256
#define OUT_F 128

__device__ float g_support[(size_t)N_NODES_MAX * OUT_F];
__device__ int   g_idx_is64;
__device__ int   g_count[N_NODES_MAX];
__device__ int   g_offsets[N_NODES_MAX];
__device__ int   g_cursor[N_NODES_MAX];
__device__ int   g_bsum[1024];
__device__ uint2 g_edges[E_MAX];            // (src, w bits), dst-bucketed

// ---------------- dtype detection -------------------------------------------
__global__ void detect_kernel(const unsigned int* __restrict__ raw)
{
    if (threadIdx.x == 0) {
        int is64 = 1;
        #pragma unroll
        for (int k = 1; k < 64; k += 2)
            if (raw[k] != 0u) { is64 = 0; break; }
        g_idx_is64 = is64;
    }
}

// ---------------- histogram over dst -----------------------------------------
__global__ void hist_kernel(const void* __restrict__ ei_raw, int E)
{
    int e = blockIdx.x * blockDim.x + threadIdx.x;
    if (e >= E) return;
    int d = g_idx_is64 ? (int)((const long long*)ei_raw)[e]
                       : ((const int*)ei_raw)[e];
    atomicAdd(&g_count[d], 1);
}

// ---------------- exclusive prefix sum ---------------------------------------
__global__ __launch_bounds__(1024) void scan1_kernel(int M)
{
    __shared__ int sh[1024];
    const int t = threadIdx.x;
    const int i = blockIdx.x * 1024 + t;
    int v = (i < M) ? g_count[i] : 0;
    sh[t] = v; __syncthreads();
    #pragma unroll
    for (int off = 1; off < 1024; off <<= 1) {
        int x = (t >= off) ? sh[t - off] : 0;
        __syncthreads(); sh[t] += x; __syncthreads();
    }
    if (i < M) g_offsets[i] = sh[t] - v;
    if (t == 1023) g_bsum[blockIdx.x] = sh[1023];
}

__global__ __launch_bounds__(1024) void scan2_kernel(int nb)
{
    __shared__ int sh[1024];
    const int t = threadIdx.x;
    int v = (t < nb) ? g_bsum[t] : 0;
    sh[t] = v; __syncthreads();
    #pragma unroll
    for (int off = 1; off < 1024; off <<= 1) {
        int x = (t >= off) ? sh[t - off] : 0;
        __syncthreads(); sh[t] += x; __syncthreads();
    }
    if (t < nb) g_bsum[t] = sh[t] - v;
}

__global__ void scan3_kernel(int M)
{
    int i = blockIdx.x * blockDim.x + threadIdx.x;
    if (i >= M) return;
    int o = g_offsets[i] + g_bsum[i >> 10];
    g_offsets[i] = o;
    g_cursor[i]  = o;
}

// ---------------- place edges into dst buckets --------------------------------
__global__ void place_kernel(const void* __restrict__ ei_raw,
                             const float* __restrict__ ew, int E)
{
    int e = blockIdx.x * blockDim.x + threadIdx.x;
    if (e >= E) return;
    int d, s;
    if (g_idx_is64) {
        const long long* ei = (const long long*)ei_raw;
        d = (int)ei[e]; s = (int)ei[(size_t)E + e];
    } else {
        const int* ei = (const int*)ei_raw;
        d = ei[e]; s = ei[(size_t)E + e];
    }
    int pos = atomicAdd(&g_cursor[d], 1);
    g_edges[pos] = make_uint2((unsigned)s, __float_as_uint(ew[e]));
}

// ---------------- tf32 helpers -----------------------------------------------
__device__ __forceinline__ uint32_t f2tf32(float f) {
    uint32_t u;
    asm("cvt.rna.tf32.f32 %0, %1;" : "=r"(u) : "f"(f));
    return u;
}
__device__ __forceinline__ void mma_tf32(
    float& c0, float& c1, float& c2, float& c3,
    uint32_t a0, uint32_t a1, uint32_t a2, uint32_t a3,
    uint32_t b0, uint32_t b1)
{
    asm volatile(
        "mma.sync.aligned.m16n8k8.row.col.f32.tf32.tf32.f32 "
        "{%0,%1,%2,%3}, {%4,%5,%6,%7}, {%8,%9}, {%0,%1,%2,%3};"
        : "+f"(c0), "+f"(c1), "+f"(c2), "+f"(c3)
        : "r"(a0), "r"(a1), "r"(a2), "r"(a3), "r"(b0), "r"(b1));
}

// ---------------- GEMM 128x128 CTA tile, tf32 mma.sync -----------------------
#define KC 32
#define PAD 36

__global__ __launch_bounds__(256) void gemm_mma_kernel(
    const float* __restrict__ X, const float* __restrict__ W,
    float* __restrict__ S, int M)
{
    __shared__ uint32_t As[128][PAD];
    __shared__ uint32_t Bs[128][PAD];

    const int t    = threadIdx.x;
    const int w    = t >> 5;
    const int lane = t & 31;
    const int g    = lane >> 2;
    const int tig  = lane & 3;
    const int wm   = (w & 3) * 32;
    const int wn   = (w >> 2) * 64;
    const int m0   = blockIdx.x * 128;

    float acc[2][8][4];
    #pragma unroll
    for (int mi = 0; mi < 2; mi++)
        #pragma unroll
        for (int ni = 0; ni < 8; ni++)
            #pragma unroll
            for (int r = 0; r < 4; r++) acc[mi][ni][r] = 0.0f;

    for (int k0 = 0; k0 < IN_F; k0 += KC) {
        #pragma unroll
        for (int i = 0; i < 4; i++) {
            int idx = t + i * 256;
            int r   = idx >> 3;
            int c   = (idx & 7) * 4;
            float4 v = make_float4(0.f, 0.f, 0.f, 0.f);
            if (m0 + r < M)
                v = *reinterpret_cast<const float4*>(
                        X + (size_t)(m0 + r) * IN_F + k0 + c);
            As[r][c + 0] = f2tf32(v.x);
            As[r][c + 1] = f2tf32(v.y);
            As[r][c + 2] = f2tf32(v.z);
            As[r][c + 3] = f2tf32(v.w);
        }
        #pragma unroll
        for (int i = 0; i < 16; i++) {
            int idx = t + i * 256;
            int k   = idx >> 7;
            int n   = idx & 127;
            Bs[n][k] = f2tf32(W[(size_t)(k0 + k) * OUT_F + n]);
        }
        __syncthreads();

        #pragma unroll
        for (int ks = 0; ks < 4; ks++) {
            const int k = ks * 8;
            uint32_t a[2][4];
            #pragma unroll
            for (int mi = 0; mi < 2; mi++) {
                int mr = wm + mi * 16 + g;
                a[mi][0] = As[mr    ][k + tig];
                a[mi][1] = As[mr + 8][k + tig];
                a[mi][2] = As[mr    ][k + tig + 4];
                a[mi][3] = As[mr + 8][k + tig + 4];
            }
            uint32_t b[8][2];
            #pragma unroll
            for (int ni = 0; ni < 8; ni++) {
                int nr = wn + ni * 8 + g;
                b[ni][0] = Bs[nr][k + tig];
                b[ni][1] = Bs[nr][k + tig + 4];
            }
            #pragma unroll
            for (int mi = 0; mi < 2; mi++)
                #pragma unroll
                for (int ni = 0; ni < 8; ni++)
                    mma_tf32(acc[mi][ni][0], acc[mi][ni][1],
                             acc[mi][ni][2], acc[mi][ni][3],
                             a[mi][0], a[mi][1], a[mi][2], a[mi][3],
                             b[ni][0], b[ni][1]);
        }
        __syncthreads();
    }

    #pragma unroll
    for (int mi = 0; mi < 2; mi++) {
        int r0 = m0 + wm + mi * 16 + g;
        #pragma unroll
        for (int ni = 0; ni < 8; ni++) {
            int c = wn + ni * 8 + tig * 2;
            if (r0 < M)
                *reinterpret_cast<float2*>(S + (size_t)r0 * OUT_F + c) =
                    make_float2(acc[mi][ni][0], acc[mi][ni][1]);
            if (r0 + 8 < M)
                *reinterpret_cast<float2*>(S + (size_t)(r0 + 8) * OUT_F + c) =
                    make_float2(acc[mi][ni][2], acc[mi][ni][3]);
        }
    }
}

// ---------------- warp-per-node aggregation -----------------------------------
__global__ __launch_bounds__(256) void aggregate_kernel(
    const float* __restrict__ S, float* __restrict__ out, int M)
{
    const int node = (blockIdx.x * blockDim.x + threadIdx.x) >> 5;
    const int lane = threadIdx.x & 31;
    if (node >= M) return;

    const int start = g_offsets[node];
    const int cnt   = g_count[node];

    float4 acc0 = make_float4(0.f, 0.f, 0.f, 0.f);
    float4 acc1 = make_float4(0.f, 0.f, 0.f, 0.f);

    for (int b = 0; b < cnt; b += 32) {
        const int nb = (cnt - b < 32) ? (cnt - b) : 32;
        uint2 p = make_uint2(0u, 0u);
        if (lane < nb) p = g_edges[start + b + lane];

        int j = 0;
        for (; j + 4 <= nb; j += 4) {
            unsigned s0 = __shfl_sync(0xffffffffu, p.x, j);
            unsigned s1 = __shfl_sync(0xffffffffu, p.x, j + 1);
            unsigned s2 = __shfl_sync(0xffffffffu, p.x, j + 2);
            unsigned s3 = __shfl_sync(0xffffffffu, p.x, j + 3);
            float w0 = __uint_as_float(__shfl_sync(0xffffffffu, p.y, j));
            float w1 = __uint_as_float(__shfl_sync(0xffffffffu, p.y, j + 1));
            float w2 = __uint_as_float(__shfl_sync(0xffffffffu, p.y, j + 2));
            float w3 = __uint_as_float(__shfl_sync(0xffffffffu, p.y, j + 3));

            float4 v0 = *reinterpret_cast<const float4*>(
                S + (size_t)s0 * OUT_F + lane * 4);
            float4 v1 = *reinterpret_cast<const float4*>(
                S + (size_t)s1 * OUT_F + lane * 4);
            float4 v2 = *reinterpret_cast<const float4*>(
                S + (size_t)s2 * OUT_F + lane * 4);
            float4 v3 = *reinterpret_cast<const float4*>(
                S + (size_t)s3 * OUT_F + lane * 4);

            acc0.x = fmaf(w0, v0.x, acc0.x); acc0.y = fmaf(w0, v0.y, acc0.y);
            acc0.z = fmaf(w0, v0.z, acc0.z); acc0.w = fmaf(w0, v0.w, acc0.w);
            acc1.x = fmaf(w1, v1.x, acc1.x); acc1.y = fmaf(w1, v1.y, acc1.y);
            acc1.z = fmaf(w1, v1.z, acc1.z); acc1.w = fmaf(w1, v1.w, acc1.w);
            acc0.x = fmaf(w2, v2.x, acc0.x); acc0.y = fmaf(w2, v2.y, acc0.y);
            acc0.z = fmaf(w2, v2.z, acc0.z); acc0.w = fmaf(w2, v2.w, acc0.w);
            acc1.x = fmaf(w3, v3.x, acc1.x); acc1.y = fmaf(w3, v3.y, acc1.y);
            acc1.z = fmaf(w3, v3.z, acc1.z); acc1.w = fmaf(w3, v3.w, acc1.w);
        }
        for (; j < nb; j++) {
            unsigned sj = __shfl_sync(0xffffffffu, p.x, j);
            float    wj = __uint_as_float(__shfl_sync(0xffffffffu, p.y, j));
            float4 v = *reinterpret_cast<const float4*>(
                S + (size_t)sj * OUT_F + lane * 4);
            acc0.x = fmaf(wj, v.x, acc0.x); acc0.y = fmaf(wj, v.y, acc0.y);
            acc0.z = fmaf(wj, v.z, acc0.z); acc0.w = fmaf(wj, v.w, acc0.w);
        }
    }
    float4 r = make_float4(acc0.x + acc1.x, acc0.y + acc1.y,
                           acc0.z + acc1.z, acc0.w + acc1.w);
    *reinterpret_cast<float4*>(out + (size_t)node * OUT_F + lane * 4) = r;
}

// ---------------------------------------------------------------------------
extern "C" void kernel_launch(void* const* d_in, const int* in_sizes, int n_in,
                              void* d_out, int out_size)
{
    const float* X  = (const float*)d_in[0];
    const void*  EI = d_in[1];
    const float* EW = (const float*)d_in[2];
    const float* W  = (const float*)d_in[3];
    float*       O  = (float*)d_out;

    const int M = out_size / OUT_F;
    const int E = in_sizes[2];

    float* S;   cudaGetSymbolAddress((void**)&S, g_support);
    int*   CNT; cudaGetSymbolAddress((void**)&CNT, g_count);

    const int nb1024 = (M + 1023) / 1024;

    // fork-join: edge pipeline on s2, GEMM on the capture (default) stream
    cudaStream_t s2;
    cudaStreamCreateWithFlags(&s2, cudaStreamNonBlocking);
    cudaEvent_t evFork, evJoin;
    cudaEventCreateWithFlags(&evFork, cudaEventDisableTiming);
    cudaEventCreateWithFlags(&evJoin, cudaEventDisableTiming);

    cudaEventRecord(evFork, 0);
    cudaStreamWaitEvent(s2, evFork, 0);

    // --- branch B (s2): edge bucketing ---
    cudaMemsetAsync(CNT, 0, (size_t)M * sizeof(int), s2);
    detect_kernel<<<1, 32, 0, s2>>>((const unsigned int*)EI);
    hist_kernel<<<(E + 255) / 256, 256, 0, s2>>>(EI, E);
    scan1_kernel<<<nb1024, 1024, 0, s2>>>(M);
    scan2_kernel<<<1, 1024, 0, s2>>>(nb1024);
    scan3_kernel<<<(M + 255) / 256, 256, 0, s2>>>(M);
    place_kernel<<<(E + 255) / 256, 256, 0, s2>>>(EI, EW, E);
    cudaEventRecord(evJoin, s2);

    // --- branch A (default stream): GEMM ---
    gemm_mma_kernel<<<(M + 127) / 128, 256>>>(X, W, S, M);

    // --- join, then aggregate ---
    cudaStreamWaitEvent(0, evJoin, 0);
    aggregate_kernel<<<(M * 32 + 255) / 256, 256>>>(S, O, M);

    cudaStreamDestroy(s2);
    cudaEventDestroy(evFork);
    cudaEventDestroy(evJoin);
}

// round 7
// speedup vs baseline: 1.7675x; 1.0928x over previous
#include <cuda_runtime.h>
#include <cuda_fp16.h>
#include <cstdint>

// ---------------------------------------------------------------------------
// GraphConvolution: out[dst] += w_e * (X @ W)[src]
// R7: support stored fp16 (halves gather traffic in aggregate); fp32 accum
//     everywhere. Fork-join graph: GEMM || edge bucketing, join at aggregate.
// ---------------------------------------------------------------------------

#define N_NODES_MAX 100000
#define E_MAX       1600000
#define IN_F  256
#define OUT_F 128

__device__ __half g_support[(size_t)N_NODES_MAX * OUT_F];
__device__ int    g_idx_is64;
__device__ int    g_count[N_NODES_MAX];
__device__ int    g_offsets[N_NODES_MAX];
__device__ int    g_cursor[N_NODES_MAX];
__device__ int    g_bsum[1024];
__device__ uint2  g_edges[E_MAX];           // (src, w bits), dst-bucketed

// ---------------- dtype detection -------------------------------------------
__global__ void detect_kernel(const unsigned int* __restrict__ raw)
{
    if (threadIdx.x == 0) {
        int is64 = 1;
        #pragma unroll
        for (int k = 1; k < 64; k += 2)
            if (raw[k] != 0u) { is64 = 0; break; }
        g_idx_is64 = is64;
    }
}

// ---------------- histogram over dst -----------------------------------------
__global__ void hist_kernel(const void* __restrict__ ei_raw, int E)
{
    int e = blockIdx.x * blockDim.x + threadIdx.x;
    if (e >= E) return;
    int d = g_idx_is64 ? (int)((const long long*)ei_raw)[e]
                       : ((const int*)ei_raw)[e];
    atomicAdd(&g_count[d], 1);
}

// ---------------- exclusive prefix sum ---------------------------------------
__global__ __launch_bounds__(1024) void scan1_kernel(int M)
{
    __shared__ int sh[1024];
    const int t = threadIdx.x;
    const int i = blockIdx.x * 1024 + t;
    int v = (i < M) ? g_count[i] : 0;
    sh[t] = v; __syncthreads();
    #pragma unroll
    for (int off = 1; off < 1024; off <<= 1) {
        int x = (t >= off) ? sh[t - off] : 0;
        __syncthreads(); sh[t] += x; __syncthreads();
    }
    if (i < M) g_offsets[i] = sh[t] - v;
    if (t == 1023) g_bsum[blockIdx.x] = sh[1023];
}

__global__ __launch_bounds__(1024) void scan2_kernel(int nb)
{
    __shared__ int sh[1024];
    const int t = threadIdx.x;
    int v = (t < nb) ? g_bsum[t] : 0;
    sh[t] = v; __syncthreads();
    #pragma unroll
    for (int off = 1; off < 1024; off <<= 1) {
        int x = (t >= off) ? sh[t - off] : 0;
        __syncthreads(); sh[t] += x; __syncthreads();
    }
    if (t < nb) g_bsum[t] = sh[t] - v;
}

__global__ void scan3_kernel(int M)
{
    int i = blockIdx.x * blockDim.x + threadIdx.x;
    if (i >= M) return;
    int o = g_offsets[i] + g_bsum[i >> 10];
    g_offsets[i] = o;
    g_cursor[i]  = o;
}

// ---------------- place edges into dst buckets --------------------------------
__global__ void place_kernel(const void* __restrict__ ei_raw,
                             const float* __restrict__ ew, int E)
{
    int e = blockIdx.x * blockDim.x + threadIdx.x;
    if (e >= E) return;
    int d, s;
    if (g_idx_is64) {
        const long long* ei = (const long long*)ei_raw;
        d = (int)ei[e]; s = (int)ei[(size_t)E + e];
    } else {
        const int* ei = (const int*)ei_raw;
        d = ei[e]; s = ei[(size_t)E + e];
    }
    int pos = atomicAdd(&g_cursor[d], 1);
    g_edges[pos] = make_uint2((unsigned)s, __float_as_uint(ew[e]));
}

// ---------------- tf32 helpers -----------------------------------------------
__device__ __forceinline__ uint32_t f2tf32(float f) {
    uint32_t u;
    asm("cvt.rna.tf32.f32 %0, %1;" : "=r"(u) : "f"(f));
    return u;
}
__device__ __forceinline__ void mma_tf32(
    float& c0, float& c1, float& c2, float& c3,
    uint32_t a0, uint32_t a1, uint32_t a2, uint32_t a3,
    uint32_t b0, uint32_t b1)
{
    asm volatile(
        "mma.sync.aligned.m16n8k8.row.col.f32.tf32.tf32.f32 "
        "{%0,%1,%2,%3}, {%4,%5,%6,%7}, {%8,%9}, {%0,%1,%2,%3};"
        : "+f"(c0), "+f"(c1), "+f"(c2), "+f"(c3)
        : "r"(a0), "r"(a1), "r"(a2), "r"(a3), "r"(b0), "r"(b1));
}

// ---------------- GEMM 128x128 CTA tile, tf32 mma.sync, fp16 store ----------
#define KC 32
#define PAD 36

__global__ __launch_bounds__(256) void gemm_mma_kernel(
    const float* __restrict__ X, const float* __restrict__ W,
    __half* __restrict__ S, int M)
{
    __shared__ uint32_t As[128][PAD];
    __shared__ uint32_t Bs[128][PAD];

    const int t    = threadIdx.x;
    const int w    = t >> 5;
    const int lane = t & 31;
    const int g    = lane >> 2;
    const int tig  = lane & 3;
    const int wm   = (w & 3) * 32;
    const int wn   = (w >> 2) * 64;
    const int m0   = blockIdx.x * 128;

    float acc[2][8][4];
    #pragma unroll
    for (int mi = 0; mi < 2; mi++)
        #pragma unroll
        for (int ni = 0; ni < 8; ni++)
            #pragma unroll
            for (int r = 0; r < 4; r++) acc[mi][ni][r] = 0.0f;

    for (int k0 = 0; k0 < IN_F; k0 += KC) {
        #pragma unroll
        for (int i = 0; i < 4; i++) {
            int idx = t + i * 256;
            int r   = idx >> 3;
            int c   = (idx & 7) * 4;
            float4 v = make_float4(0.f, 0.f, 0.f, 0.f);
            if (m0 + r < M)
                v = *reinterpret_cast<const float4*>(
                        X + (size_t)(m0 + r) * IN_F + k0 + c);
            As[r][c + 0] = f2tf32(v.x);
            As[r][c + 1] = f2tf32(v.y);
            As[r][c + 2] = f2tf32(v.z);
            As[r][c + 3] = f2tf32(v.w);
        }
        #pragma unroll
        for (int i = 0; i < 16; i++) {
            int idx = t + i * 256;
            int k   = idx >> 7;
            int n   = idx & 127;
            Bs[n][k] = f2tf32(W[(size_t)(k0 + k) * OUT_F + n]);
        }
        __syncthreads();

        #pragma unroll
        for (int ks = 0; ks < 4; ks++) {
            const int k = ks * 8;
            uint32_t a[2][4];
            #pragma unroll
            for (int mi = 0; mi < 2; mi++) {
                int mr = wm + mi * 16 + g;
                a[mi][0] = As[mr    ][k + tig];
                a[mi][1] = As[mr + 8][k + tig];
                a[mi][2] = As[mr    ][k + tig + 4];
                a[mi][3] = As[mr + 8][k + tig + 4];
            }
            uint32_t b[8][2];
            #pragma unroll
            for (int ni = 0; ni < 8; ni++) {
                int nr = wn + ni * 8 + g;
                b[ni][0] = Bs[nr][k + tig];
                b[ni][1] = Bs[nr][k + tig + 4];
            }
            #pragma unroll
            for (int mi = 0; mi < 2; mi++)
                #pragma unroll
                for (int ni = 0; ni < 8; ni++)
                    mma_tf32(acc[mi][ni][0], acc[mi][ni][1],
                             acc[mi][ni][2], acc[mi][ni][3],
                             a[mi][0], a[mi][1], a[mi][2], a[mi][3],
                             b[ni][0], b[ni][1]);
        }
        __syncthreads();
    }

    #pragma unroll
    for (int mi = 0; mi < 2; mi++) {
        int r0 = m0 + wm + mi * 16 + g;
        #pragma unroll
        for (int ni = 0; ni < 8; ni++) {
            int c = wn + ni * 8 + tig * 2;
            if (r0 < M)
                *reinterpret_cast<__half2*>(S + (size_t)r0 * OUT_F + c) =
                    __floats2half2_rn(acc[mi][ni][0], acc[mi][ni][1]);
            if (r0 + 8 < M)
                *reinterpret_cast<__half2*>(S + (size_t)(r0 + 8) * OUT_F + c) =
                    __floats2half2_rn(acc[mi][ni][2], acc[mi][ni][3]);
        }
    }
}

// ---------------- warp-per-node aggregation (fp16 gather, fp32 accum) --------
__global__ __launch_bounds__(256) void aggregate_kernel(
    const __half* __restrict__ S, float* __restrict__ out, int M)
{
    const int node = (blockIdx.x * blockDim.x + threadIdx.x) >> 5;
    const int lane = threadIdx.x & 31;
    if (node >= M) return;

    const int start = g_offsets[node];
    const int cnt   = g_count[node];

    float4 acc0 = make_float4(0.f, 0.f, 0.f, 0.f);
    float4 acc1 = make_float4(0.f, 0.f, 0.f, 0.f);

    for (int b = 0; b < cnt; b += 32) {
        const int nb = (cnt - b < 32) ? (cnt - b) : 32;
        uint2 p = make_uint2(0u, 0u);
        if (lane < nb) p = g_edges[start + b + lane];

        int j = 0;
        for (; j + 4 <= nb; j += 4) {
            unsigned s0 = __shfl_sync(0xffffffffu, p.x, j);
            unsigned s1 = __shfl_sync(0xffffffffu, p.x, j + 1);
            unsigned s2 = __shfl_sync(0xffffffffu, p.x, j + 2);
            unsigned s3 = __shfl_sync(0xffffffffu, p.x, j + 3);
            float w0 = __uint_as_float(__shfl_sync(0xffffffffu, p.y, j));
            float w1 = __uint_as_float(__shfl_sync(0xffffffffu, p.y, j + 1));
            float w2 = __uint_as_float(__shfl_sync(0xffffffffu, p.y, j + 2));
            float w3 = __uint_as_float(__shfl_sync(0xffffffffu, p.y, j + 3));

            uint2 r0 = *reinterpret_cast<const uint2*>(
                S + (size_t)s0 * OUT_F + lane * 4);
            uint2 r1 = *reinterpret_cast<const uint2*>(
                S + (size_t)s1 * OUT_F + lane * 4);
            uint2 r2 = *reinterpret_cast<const uint2*>(
                S + (size_t)s2 * OUT_F + lane * 4);
            uint2 r3 = *reinterpret_cast<const uint2*>(
                S + (size_t)s3 * OUT_F + lane * 4);

            float2 a, bb;
            a  = __half22float2(*reinterpret_cast<__half2*>(&r0.x));
            bb = __half22float2(*reinterpret_cast<__half2*>(&r0.y));
            acc0.x = fmaf(w0, a.x,  acc0.x); acc0.y = fmaf(w0, a.y,  acc0.y);
            acc0.z = fmaf(w0, bb.x, acc0.z); acc0.w = fmaf(w0, bb.y, acc0.w);
            a  = __half22float2(*reinterpret_cast<__half2*>(&r1.x));
            bb = __half22float2(*reinterpret_cast<__half2*>(&r1.y));
            acc1.x = fmaf(w1, a.x,  acc1.x); acc1.y = fmaf(w1, a.y,  acc1.y);
            acc1.z = fmaf(w1, bb.x, acc1.z); acc1.w = fmaf(w1, bb.y, acc1.w);
            a  = __half22float2(*reinterpret_cast<__half2*>(&r2.x));
            bb = __half22float2(*reinterpret_cast<__half2*>(&r2.y));
            acc0.x = fmaf(w2, a.x,  acc0.x); acc0.y = fmaf(w2, a.y,  acc0.y);
            acc0.z = fmaf(w2, bb.x, acc0.z); acc0.w = fmaf(w2, bb.y, acc0.w);
            a  = __half22float2(*reinterpret_cast<__half2*>(&r3.x));
            bb = __half22float2(*reinterpret_cast<__half2*>(&r3.y));
            acc1.x = fmaf(w3, a.x,  acc1.x); acc1.y = fmaf(w3, a.y,  acc1.y);
            acc1.z = fmaf(w3, bb.x, acc1.z); acc1.w = fmaf(w3, bb.y, acc1.w);
        }
        for (; j < nb; j++) {
            unsigned sj = __shfl_sync(0xffffffffu, p.x, j);
            float    wj = __uint_as_float(__shfl_sync(0xffffffffu, p.y, j));
            uint2 r = *reinterpret_cast<const uint2*>(
                S + (size_t)sj * OUT_F + lane * 4);
            float2 a  = __half22float2(*reinterpret_cast<__half2*>(&r.x));
            float2 bb = __half22float2(*reinterpret_cast<__half2*>(&r.y));
            acc0.x = fmaf(wj, a.x,  acc0.x); acc0.y = fmaf(wj, a.y,  acc0.y);
            acc0.z = fmaf(wj, bb.x, acc0.z); acc0.w = fmaf(wj, bb.y, acc0.w);
        }
    }
    float4 r = make_float4(acc0.x + acc1.x, acc0.y + acc1.y,
                           acc0.z + acc1.z, acc0.w + acc1.w);
    *reinterpret_cast<float4*>(out + (size_t)node * OUT_F + lane * 4) = r;
}

// ---------------------------------------------------------------------------
extern "C" void kernel_launch(void* const* d_in, const int* in_sizes, int n_in,
                              void* d_out, int out_size)
{
    const float* X  = (const float*)d_in[0];
    const void*  EI = d_in[1];
    const float* EW = (const float*)d_in[2];
    const float* W  = (const float*)d_in[3];
    float*       O  = (float*)d_out;

    const int M = out_size / OUT_F;
    const int E = in_sizes[2];

    __half* S;  cudaGetSymbolAddress((void**)&S, g_support);
    int*   CNT; cudaGetSymbolAddress((void**)&CNT, g_count);

    const int nb1024 = (M + 1023) / 1024;

    cudaStream_t s2;
    cudaStreamCreateWithFlags(&s2, cudaStreamNonBlocking);
    cudaEvent_t evFork, evJoin;
    cudaEventCreateWithFlags(&evFork, cudaEventDisableTiming);
    cudaEventCreateWithFlags(&evJoin, cudaEventDisableTiming);

    cudaEventRecord(evFork, 0);
    cudaStreamWaitEvent(s2, evFork, 0);

    // --- branch B (s2): edge bucketing ---
    cudaMemsetAsync(CNT, 0, (size_t)M * sizeof(int), s2);
    detect_kernel<<<1, 32, 0, s2>>>((const unsigned int*)EI);
    hist_kernel<<<(E + 255) / 256, 256, 0, s2>>>(EI, E);
    scan1_kernel<<<nb1024, 1024, 0, s2>>>(M);
    scan2_kernel<<<1, 1024, 0, s2>>>(nb1024);
    scan3_kernel<<<(M + 255) / 256, 256, 0, s2>>>(M);
    place_kernel<<<(E + 255) / 256, 256, 0, s2>>>(EI, EW, E);
    cudaEventRecord(evJoin, s2);

    // --- branch A (default stream): GEMM ---
    gemm_mma_kernel<<<(M + 127) / 128, 256>>>(X, W, S, M);

    // --- join, then aggregate ---
    cudaStreamWaitEvent(0, evJoin, 0);
    aggregate_kernel<<<(M * 32 + 255) / 256, 256>>>(S, O, M);

    cudaStreamDestroy(s2);
    cudaEventDestroy(evFork);
    cudaEventDestroy(evJoin);
}